// round 16
// baseline (speedup 1.0000x reference)
#include <cuda_runtime.h>
#include <cuda_bf16.h>
#include <cstdint>

#define B_ROOT   8192
#define KFAN     16
#define NCHILD   (B_ROOT * KFAN)     // 131072
#define VOCAB    50000
#define DIM      64
#define CR       8
#define NR       64
#define CC       16
#define NC       128
#define OUTD     32
#define KDIM     (CC * DIM + NC)     // 1152
#define OUTCOLS  (CR * DIM + NR + OUTD)  // 608
#define EPSBN    1e-5f

#define SC_BLKS   (NCHILD / 256)                    // 512
#define SR_BLKS   (B_ROOT / 128)                    // 64
#define RE_BLKS   (B_ROOT / 8)                      // 1024 root-emb blocks
#define PTILES    ((VOCAB + 127) / 128)             // 391
#define PROJ_BLKS (CC * PTILES)                     // 6256
#define RE_BASE   (SC_BLKS + SR_BLKS)               // 576
#define PJ_BASE   (RE_BASE + RE_BLKS)               // 1600
#define BIG1_BLKS (PJ_BASE + PROJ_BLKS)             // 7856

#define CH_BLKS   (B_ROOT / 8)                      // 1024 (8 roots / 256-thr block)
#define RN_BLKS   (B_ROOT / 32)                     // 256 root-num blocks
#define BIG2_BLKS (CH_BLKS + RN_BLKS)               // 1280

// big1 proj smem: Ws[64][40] + 8 warps * As[16][68]
#define WS_FLOATS   (DIM * 40)                      // 2560
#define AS_FLOATS   (16 * 68)                       // 1088
#define BIG1_SMEM   ((WS_FLOATS + 8 * AS_FLOATS) * 4)   // 45056 B

// big2 smem: Wn_s[128][40] + a_c[128] + s_c[128] + 8 warps * { hs[16][68] (alias buf), cats[256], gs[16], pad }
#define WNS_FLOATS  (NC * 40)                       // 5120
#define BNC_FLOATS  (2 * NC)                        // 256
#define W2_FLOATS   (16 * 68 + 256 + 16 + 16)       // 1376
#define BIG2_SMEM   ((WNS_FLOATS + BNC_FLOATS + 8 * W2_FLOATS) * 4)  // 65536 B -> 3 blocks/SM

// ---------------- scratch (device globals; allocation-free) ----------------
__device__ __align__(16) double g_sum_c[NC];
__device__ __align__(16) double g_ss_c [NC];
__device__ __align__(16) double g_sum_r[NR];
__device__ __align__(16) double g_ss_r [NR];
// bf16-packed categorical projection: 16 bf16x2 words per (c,v) row = 64 B
__device__ __align__(256) unsigned g_projp[CC * VOCAB * (OUTD / 2)];   // 51.2 MB

// ---------------- helpers ----------------
__device__ __forceinline__ unsigned tf32r(float x) {
    unsigned u;
    asm("cvt.rna.tf32.f32 %0, %1;" : "=r"(u) : "f"(x));
    return u;
}
__device__ __forceinline__ void mma_tf32(float& d0, float& d1, float& d2, float& d3,
                                         unsigned a0, unsigned a1, unsigned a2, unsigned a3,
                                         unsigned b0, unsigned b1) {
    asm volatile("mma.sync.aligned.m16n8k8.row.col.f32.tf32.tf32.f32 "
        "{%0,%1,%2,%3}, {%4,%5,%6,%7}, {%8,%9}, {%0,%1,%2,%3};"
        : "+f"(d0), "+f"(d1), "+f"(d2), "+f"(d3)
        : "r"(a0), "r"(a1), "r"(a2), "r"(a3), "r"(b0), "r"(b1));
}
// accumulate a uint4 of bf16x2 (8 outputs) into 8 fp32 accs
__device__ __forceinline__ void acc8(float* s, uint4 u) {
    unsigned w[4] = {u.x, u.y, u.z, u.w};
#pragma unroll
    for (int j = 0; j < 4; ++j) {
        __nv_bfloat162 b2 = *reinterpret_cast<__nv_bfloat162*>(&w[j]);
        float2 f = __bfloat1622float2(b2);
        s[2 * j]     += f.x;
        s[2 * j + 1] += f.y;
    }
}
__device__ __forceinline__ unsigned packbf(float lo, float hi) {
    __nv_bfloat162 b2 = __float22bfloat162_rn(make_float2(lo, hi));
    return *reinterpret_cast<unsigned*>(&b2);
}

// ---------------- kernel 0: reset ----------------
__global__ void k_reset() {
    int t = threadIdx.x;
    if (t < NC) { g_sum_c[t] = 0.0; g_ss_c[t] = 0.0; }
    if (t < NR) { g_sum_r[t] = 0.0; g_ss_r[t] = 0.0; }
}

// ---------------- kernel 1: big1 = stats_child ∪ stats_root ∪ root_emb ∪ proj(mma) ----
__global__ __launch_bounds__(256)
void k_big1(const int* __restrict__ cfi, const float* __restrict__ child_num,
            const int* __restrict__ idx, const float* __restrict__ root_num,
            const int* __restrict__ root_cat, const float* __restrict__ emb_root,
            const float* __restrict__ emb_child, const float* __restrict__ W,
            float* __restrict__ out) {
    extern __shared__ float sm[];
    int bid = blockIdx.x;
    int t = threadIdx.x;
    int lane = t & 31;
    int warp = t >> 5;

    if (bid < SC_BLKS) {
        int* rid = (int*)sm;
        rid[t] = cfi[bid * 256 + t];
        __syncthreads();
        int col = t & 127;
        int r0 = (t >> 7) * 128;
        float s[8], ss[8];
#pragma unroll
        for (int u = 0; u < 8; ++u) { s[u] = 0.f; ss[u] = 0.f; }
        for (int r = r0; r < r0 + 128; r += 8) {
            float x[8];
#pragma unroll
            for (int u = 0; u < 8; ++u) {
                int g = rid[r + u];
                x[u] = __ldg(&child_num[(size_t)g * NC + col]);
            }
#pragma unroll
            for (int u = 0; u < 8; ++u) { s[u] += x[u]; ss[u] += x[u] * x[u]; }
        }
        float st  = (s[0]+s[1])+(s[2]+s[3])+((s[4]+s[5])+(s[6]+s[7]));
        float sst = (ss[0]+ss[1])+(ss[2]+ss[3])+((ss[4]+ss[5])+(ss[6]+ss[7]));
        atomicAdd(&g_sum_c[col], (double)st);
        atomicAdd(&g_ss_c[col],  (double)sst);
        return;
    }
    if (bid < RE_BASE) {
        int b = bid - SC_BLKS;
        int* rid = (int*)sm;
        if (t < 128) rid[t] = idx[b * 128 + t];
        __syncthreads();
        int col = t & 63;
        int r0 = (t >> 6) * 32;
        float s[4], ss[4];
#pragma unroll
        for (int u = 0; u < 4; ++u) { s[u] = 0.f; ss[u] = 0.f; }
        for (int r = r0; r < r0 + 32; r += 4) {
            float x[4];
#pragma unroll
            for (int u = 0; u < 4; ++u) {
                int g = rid[r + u];
                x[u] = __ldg(&root_num[(size_t)g * NR + col]);
            }
#pragma unroll
            for (int u = 0; u < 4; ++u) { s[u] += x[u]; ss[u] += x[u] * x[u]; }
        }
        atomicAdd(&g_sum_r[col], (double)((s[0]+s[1])+(s[2]+s[3])));
        atomicAdd(&g_ss_r[col],  (double)((ss[0]+ss[1])+(ss[2]+ss[3])));
        return;
    }
    if (bid < PJ_BASE) {
        // ---- root embedding copy: one warp per root row ----
        int rr = (bid - RE_BASE) * 8 + warp;
        int g = idx[rr];
        const int* cr = root_cat + (size_t)g * CR;
        float* orow = out + (size_t)rr * OUTCOLS;
#pragma unroll
        for (int c = 0; c < CR; ++c) {
            int v = cr[c];
            const float2* e = (const float2*)(emb_root + ((size_t)c * VOCAB + v) * DIM);
            *(float2*)(orow + c * DIM + lane * 2) = e[lane];
        }
        return;
    }

    // ---- proj via mma tf32: block = (c, 128 vocab rows); warp = 16 rows ----
    int pb = bid - PJ_BASE;
    int c  = pb / PTILES;
    int vbase = (pb % PTILES) * 128;

    float* Ws = sm;                               // [64][40] tf32 bits
    float* As = sm + WS_FLOATS + warp * AS_FLOATS;// [16][68] tf32 bits

    for (int i = t; i < DIM * OUTD; i += 256) {
        int o = i >> 6, d = i & 63;
        Ws[d * 40 + o] = __uint_as_float(tf32r(W[(size_t)o * KDIM + c * DIM + d]));
    }
    __syncthreads();

    int v0w = vbase + warp * 16;
    {
        int rsel = lane >> 4;
        int col  = (lane & 15) * 4;
#pragma unroll
        for (int rr = 0; rr < 8; ++rr) {
            int row = 2 * rr + rsel;
            int v = v0w + row;
            float4 e = make_float4(0.f, 0.f, 0.f, 0.f);
            if (v < VOCAB)
                e = *(const float4*)(emb_child + ((size_t)c * VOCAB + v) * DIM + col);
            float4 a;
            a.x = __uint_as_float(tf32r(e.x));
            a.y = __uint_as_float(tf32r(e.y));
            a.z = __uint_as_float(tf32r(e.z));
            a.w = __uint_as_float(tf32r(e.w));
            *(float4*)(As + row * 68 + col) = a;
        }
    }
    __syncwarp();

    float cfr[4][4];
#pragma unroll
    for (int nt = 0; nt < 4; ++nt)
#pragma unroll
        for (int j = 0; j < 4; ++j) cfr[nt][j] = 0.f;

    int gid = lane >> 2, tig = lane & 3;
#pragma unroll
    for (int kt = 0; kt < 8; ++kt) {
        int k0 = kt * 8;
        unsigned a0 = __float_as_uint(As[gid * 68 + k0 + tig]);
        unsigned a1 = __float_as_uint(As[(gid + 8) * 68 + k0 + tig]);
        unsigned a2 = __float_as_uint(As[gid * 68 + k0 + tig + 4]);
        unsigned a3 = __float_as_uint(As[(gid + 8) * 68 + k0 + tig + 4]);
#pragma unroll
        for (int nt = 0; nt < 4; ++nt) {
            unsigned b0 = __float_as_uint(Ws[(k0 + tig) * 40 + nt * 8 + gid]);
            unsigned b1 = __float_as_uint(Ws[(k0 + tig + 4) * 40 + nt * 8 + gid]);
            mma_tf32(cfr[nt][0], cfr[nt][1], cfr[nt][2], cfr[nt][3],
                     a0, a1, a2, a3, b0, b1);
        }
    }
    __syncwarp();

    // epilogue: repack fragments via smem (As dead) -> coalesced uint4 stores
    {
        unsigned* Au = (unsigned*)As;   // [16][20] pitch
#pragma unroll
        for (int nt = 0; nt < 4; ++nt) {
            int word = nt * 4 + tig;
            Au[gid * 20 + word]       = packbf(cfr[nt][0], cfr[nt][1]);
            Au[(gid + 8) * 20 + word] = packbf(cfr[nt][2], cfr[nt][3]);
        }
        __syncwarp();
        int row = lane >> 1, q = lane & 1;
        int v = v0w + row;
        if (v < VOCAB) {
            unsigned* dst = g_projp + ((size_t)c * VOCAB + v) * 16;
            *(uint4*)(dst + q * 4)       = *(uint4*)(Au + row * 20 + q * 4);
            *(uint4*)(dst + (q + 2) * 4) = *(uint4*)(Au + row * 20 + (q + 2) * 4);
        }
    }
}

// ---------------- kernel 2: big2 = child (inline BN-coeffs) ∪ root-num ----------------
__global__ __launch_bounds__(256, 3)
void k_big2(const int* __restrict__ cfi, const int* __restrict__ child_cat,
            const float* __restrict__ child_num,
            const int* __restrict__ idx, const float* __restrict__ root_num,
            const float* __restrict__ gamma_c, const float* __restrict__ beta_c,
            const float* __restrict__ gamma_r, const float* __restrict__ beta_r,
            const float* __restrict__ W, const float* __restrict__ bias,
            float* __restrict__ out) {
    extern __shared__ float sm[];
    int bid = blockIdx.x;
    int t = threadIdx.x;
    int lane = t & 31;
    int warp = t >> 5;

    if (bid >= CH_BLKS) {
        // ---- root numeric BN: compute a_r/s_r in smem, then 32 rows per block ----
        float* a_r = sm;            // [64]
        float* s_r = sm + 64;       // [64]
        if (t < NR) {
            double mu = g_sum_r[t] * (1.0 / (double)B_ROOT);
            double v  = g_ss_r[t] * (1.0 / (double)B_ROOT) - mu * mu;
            float a = gamma_r[t] * rsqrtf((float)v + EPSBN);
            a_r[t] = a;
            s_r[t] = beta_r[t] - (float)mu * a;
        }
        __syncthreads();
        int r = (bid - CH_BLKS) * 32 + (t >> 3);
        int g = idx[r];
        int c8 = (t & 7) * 8;
        float4 x0 = *(const float4*)(root_num + (size_t)g * NR + c8);
        float4 x1 = *(const float4*)(root_num + (size_t)g * NR + c8 + 4);
        float4 a0 = *(const float4*)(a_r + c8);
        float4 a1 = *(const float4*)(a_r + c8 + 4);
        float4 s0 = *(const float4*)(s_r + c8);
        float4 s1 = *(const float4*)(s_r + c8 + 4);
        float4 y0, y1;
        y0.x = fmaf(x0.x, a0.x, s0.x); y0.y = fmaf(x0.y, a0.y, s0.y);
        y0.z = fmaf(x0.z, a0.z, s0.z); y0.w = fmaf(x0.w, a0.w, s0.w);
        y1.x = fmaf(x1.x, a1.x, s1.x); y1.y = fmaf(x1.y, a1.y, s1.y);
        y1.z = fmaf(x1.z, a1.z, s1.z); y1.w = fmaf(x1.w, a1.w, s1.w);
        float* orow = out + (size_t)r * OUTCOLS + CR * DIM;
        *(float4*)(orow + c8)     = y0;
        *(float4*)(orow + c8 + 4) = y1;
        return;
    }

    // ---- child: warp = one root (16 rows) ----
    float* Wn_s = sm;                                   // [128][40] tf32 bits
    float* a_c  = sm + WNS_FLOATS;                      // [128]
    float* s_c  = a_c + NC;                             // [128]
    float* wb   = sm + WNS_FLOATS + BNC_FLOATS + warp * W2_FLOATS;
    float* hs   = wb;                                   // [16][68] (alias buf[16][36])
    float* buf  = hs;
    int*   cats = (int*)(wb + 16 * 68);                 // [16][16]
    int*   gs   = cats + 256;                           // [16]

    int root = bid * 8 + warp;

    // front-load the scattered index chain (hidden under staging below)
    if (lane < 16) gs[lane] = cfi[root * KFAN + lane];
    __syncwarp();
    {
        int e1 = lane, e2 = lane + 32;
        ((int4*)cats)[e1] = ((const int4*)(child_cat + (size_t)gs[e1 >> 2] * CC))[e1 & 3];
        ((int4*)cats)[e2] = ((const int4*)(child_cat + (size_t)gs[e2 >> 2] * CC))[e2 & 3];
    }

    // block staging: Wn_s = tf32(W numeric slice) (pure function of W);
    // BN coeffs a_c/s_c from double stats (identical formula/order to prior finalize)
    for (int i = t; i < NC * OUTD; i += 256) {
        int k = i >> 5, o = i & 31;
        Wn_s[k * 40 + o] = __uint_as_float(tf32r(W[(size_t)o * KDIM + CC * DIM + k]));
    }
    if (t < NC) {
        double mu = g_sum_c[t] * (1.0 / (double)NCHILD);
        double v  = g_ss_c[t] * (1.0 / (double)NCHILD) - mu * mu;
        float a = gamma_c[t] * rsqrtf((float)v + EPSBN);
        a_c[t] = a;
        s_c[t] = beta_c[t] - (float)mu * a;
    }
    __syncthreads();

    // cooperative cat gather
    float s[16];
#pragma unroll
    for (int j = 0; j < 16; ++j) s[j] = 0.f;
    int rA = lane >> 2, m = lane & 3, rB = rA + 8;
#pragma unroll
    for (int c = 0; c < CC; ++c) {
        uint4 ua = ((const uint4*)(g_projp + ((size_t)c * VOCAB + cats[rA * 16 + c]) * 16))[m];
        uint4 ub = ((const uint4*)(g_projp + ((size_t)c * VOCAB + cats[rB * 16 + c]) * 16))[m];
        acc8(s, ua);
        acc8(s + 8, ub);
    }

    // numeric GEMM [16x128]@[128x32] via tf32 MMA, k staged in 2 chunks of 64
    float cfr[4][4];
#pragma unroll
    for (int nt = 0; nt < 4; ++nt)
#pragma unroll
        for (int j = 0; j < 4; ++j) cfr[nt][j] = 0.f;

    int gid = lane >> 2, tig = lane & 3;
    int cg  = lane & 15, rof = lane >> 4;
#pragma unroll
    for (int kh = 0; kh < 2; ++kh) {
        __syncwarp();
        float4 a4 = *(const float4*)(a_c + kh * 64 + cg * 4);
        float4 s4 = *(const float4*)(s_c + kh * 64 + cg * 4);
#pragma unroll
        for (int j = 0; j < 8; ++j) {
            int r = j * 2 + rof;
            float4 x = *(const float4*)(child_num + (size_t)gs[r] * NC + kh * 64 + cg * 4);
            uint4 hv;
            hv.x = tf32r(fmaf(x.x, a4.x, s4.x));
            hv.y = tf32r(fmaf(x.y, a4.y, s4.y));
            hv.z = tf32r(fmaf(x.z, a4.z, s4.z));
            hv.w = tf32r(fmaf(x.w, a4.w, s4.w));
            *(uint4*)(hs + r * 68 + cg * 4) = hv;
        }
        __syncwarp();
#pragma unroll
        for (int kt = 0; kt < 8; ++kt) {
            int k0 = kt * 8;
            unsigned a0 = __float_as_uint(hs[gid * 68 + k0 + tig]);
            unsigned a1 = __float_as_uint(hs[(gid + 8) * 68 + k0 + tig]);
            unsigned a2 = __float_as_uint(hs[gid * 68 + k0 + tig + 4]);
            unsigned a3 = __float_as_uint(hs[(gid + 8) * 68 + k0 + tig + 4]);
            int kg = kh * 64 + k0 + tig;
#pragma unroll
            for (int nt = 0; nt < 4; ++nt) {
                unsigned b0 = __float_as_uint(Wn_s[kg * 40 + nt * 8 + gid]);
                unsigned b1 = __float_as_uint(Wn_s[(kg + 4) * 40 + nt * 8 + gid]);
                mma_tf32(cfr[nt][0], cfr[nt][1], cfr[nt][2], cfr[nt][3],
                         a0, a1, a2, a3, b0, b1);
            }
        }
    }
    __syncwarp();

    // cat partials -> buf (aliases hs; all MMA reads done)
    *(float4*)(buf + rA * 36 + 8 * m)     = make_float4(s[0], s[1], s[2], s[3]);
    *(float4*)(buf + rA * 36 + 8 * m + 4) = make_float4(s[4], s[5], s[6], s[7]);
    *(float4*)(buf + rB * 36 + 8 * m)     = make_float4(s[8], s[9], s[10], s[11]);
    *(float4*)(buf + rB * 36 + 8 * m + 4) = make_float4(s[12], s[13], s[14], s[15]);
    __syncwarp();

    // add MMA fragments (distinct (r,o) owners)
#pragma unroll
    for (int nt = 0; nt < 4; ++nt) {
        int o0 = nt * 8 + 2 * tig;
        buf[gid * 36 + o0]           += cfr[nt][0];
        buf[gid * 36 + o0 + 1]       += cfr[nt][1];
        buf[(gid + 8) * 36 + o0]     += cfr[nt][2];
        buf[(gid + 8) * 36 + o0 + 1] += cfr[nt][3];
    }
    __syncwarp();

    // epilogue: lane = output column; relu + mean over 16 rows; coalesced store
    {
        float bp = __ldg(&bias[lane]);
        float acc = 0.f;
#pragma unroll
        for (int r = 0; r < 16; ++r)
            acc += fmaxf(buf[r * 36 + lane] + bp, 0.f);
        out[(size_t)root * OUTCOLS + CR * DIM + NR + lane] = acc * (1.0f / (float)KFAN);
    }
}

// ---------------- launch ----------------
extern "C" void kernel_launch(void* const* d_in, const int* in_sizes, int n_in,
                              void* d_out, int out_size) {
    const int *idx = nullptr, *cfi = nullptr, *root_cat = nullptr, *child_cat = nullptr;
    const float *root_num = nullptr, *child_num = nullptr;
    const float *emb_root = nullptr, *emb_child = nullptr;
    const float *W = nullptr, *bias = nullptr;
    const float *gamma_r = nullptr, *beta_r = nullptr, *gamma_c = nullptr, *beta_c = nullptr;

    for (int i = 0; i < n_in; ++i) {
        long long s = in_sizes[i];
        void* p = d_in[i];
        switch (s) {
            case 8192:      idx = (const int*)p; break;
            case 131072:    cfi = (const int*)p; break;
            case 1600000:   root_cat  = (const int*)p; break;
            case 8000000:   child_cat = (const int*)p; break;
            case 12800000:  root_num  = (const float*)p; break;
            case 64000000:  child_num = (const float*)p; break;
            case 25600000:  emb_root  = (const float*)p; break;
            case 51200000:  emb_child = (const float*)p; break;
            case 36864:     W = (const float*)p; break;
            case 32:        bias = (const float*)p; break;
            case 64:
                if (!gamma_r) gamma_r = (const float*)p; else beta_r = (const float*)p;
                break;
            case 128:
                if (!gamma_c) gamma_c = (const float*)p; else beta_c = (const float*)p;
                break;
            default: break;
        }
    }

    float* out = (float*)d_out;

    cudaFuncSetAttribute(k_big1, cudaFuncAttributeMaxDynamicSharedMemorySize, BIG1_SMEM);
    cudaFuncSetAttribute(k_big2, cudaFuncAttributeMaxDynamicSharedMemorySize, BIG2_SMEM);

    k_reset<<<1, 256>>>();
    k_big1<<<BIG1_BLKS, 256, BIG1_SMEM>>>(cfi, child_num, idx, root_num,
                                          root_cat, emb_root, emb_child, W, out);
    k_big2<<<BIG2_BLKS, 256, BIG2_SMEM>>>(cfi, child_cat, child_num,
                                          idx, root_num,
                                          gamma_c, beta_c, gamma_r, beta_r,
                                          W, bias, out);
}

// round 17
// speedup vs baseline: 1.0664x; 1.0664x over previous
#include <cuda_runtime.h>
#include <cuda_bf16.h>
#include <cstdint>

#define B_ROOT   8192
#define KFAN     16
#define NCHILD   (B_ROOT * KFAN)     // 131072
#define VOCAB    50000
#define DIM      64
#define CR       8
#define NR       64
#define CC       16
#define NC       128
#define OUTD     32
#define KDIM     (CC * DIM + NC)     // 1152
#define OUTCOLS  (CR * DIM + NR + OUTD)  // 608
#define EPSBN    1e-5f

#define SC_BLKS   (NCHILD / 256)                    // 512
#define SR_BLKS   (B_ROOT / 128)                    // 64
#define RE_BLKS   (B_ROOT / 8)                      // 1024 root-emb blocks
#define PTILES    ((VOCAB + 127) / 128)             // 391
#define PROJ_BLKS (CC * PTILES)                     // 6256
#define RE_BASE   (SC_BLKS + SR_BLKS)               // 576
#define PJ_BASE   (RE_BASE + RE_BLKS)               // 1600
#define BIG1_BLKS (PJ_BASE + PROJ_BLKS)             // 7856

#define CH_BLKS   (B_ROOT / 8)                      // 1024 (8 roots / 256-thr block)
#define RN_BLKS   (B_ROOT / 32)                     // 256 root-num blocks
#define BIG2_BLKS (CH_BLKS + RN_BLKS)               // 1280

// big1 proj smem: Ws[64][40] + 8 warps * As[16][68]
#define WS_FLOATS   (DIM * 40)                      // 2560
#define AS_FLOATS   (16 * 68)                       // 1088
#define BIG1_SMEM   ((WS_FLOATS + 8 * AS_FLOATS) * 4)   // 45056 B

// big2 smem (R13/R15-proven): Wn_s[128][40] + 8 warps * { hs[16][68] (alias buf), cats[256], gs[16], pad }
#define WNS_FLOATS  (NC * 40)                       // 5120
#define W2_FLOATS   (16 * 68 + 256 + 16 + 16)       // 1376
#define BIG2_SMEM   ((WNS_FLOATS + 8 * W2_FLOATS) * 4)  // 64512 B -> 3 blocks/SM

// ---------------- scratch (device globals; allocation-free) ----------------
__device__ __align__(16) double g_sum_c[NC];
__device__ __align__(16) double g_ss_c [NC];
__device__ __align__(16) double g_sum_r[NR];
__device__ __align__(16) double g_ss_r [NR];
__device__ __align__(16) float g_a_c[NC];
__device__ __align__(16) float g_s_c[NC];
__device__ __align__(16) float g_a_r[NR];
__device__ __align__(16) float g_s_r[NR];
__device__ __align__(16) float g_wt[NC * OUTD];   // tf32-rounded numeric W slice [k][o]
// bf16-packed categorical projection: 16 bf16x2 words per (c,v) row = 64 B
__device__ __align__(256) unsigned g_projp[CC * VOCAB * (OUTD / 2)];   // 51.2 MB

// ---------------- helpers ----------------
__device__ __forceinline__ unsigned tf32r(float x) {
    unsigned u;
    asm("cvt.rna.tf32.f32 %0, %1;" : "=r"(u) : "f"(x));
    return u;
}
__device__ __forceinline__ void mma_tf32(float& d0, float& d1, float& d2, float& d3,
                                         unsigned a0, unsigned a1, unsigned a2, unsigned a3,
                                         unsigned b0, unsigned b1) {
    asm volatile("mma.sync.aligned.m16n8k8.row.col.f32.tf32.tf32.f32 "
        "{%0,%1,%2,%3}, {%4,%5,%6,%7}, {%8,%9}, {%0,%1,%2,%3};"
        : "+f"(d0), "+f"(d1), "+f"(d2), "+f"(d3)
        : "r"(a0), "r"(a1), "r"(a2), "r"(a3), "r"(b0), "r"(b1));
}
// accumulate a uint4 of bf16x2 (8 outputs) into 8 fp32 accs
__device__ __forceinline__ void acc8(float* s, uint4 u) {
    unsigned w[4] = {u.x, u.y, u.z, u.w};
#pragma unroll
    for (int j = 0; j < 4; ++j) {
        __nv_bfloat162 b2 = *reinterpret_cast<__nv_bfloat162*>(&w[j]);
        float2 f = __bfloat1622float2(b2);
        s[2 * j]     += f.x;
        s[2 * j + 1] += f.y;
    }
}
__device__ __forceinline__ unsigned packbf(float lo, float hi) {
    __nv_bfloat162 b2 = __float22bfloat162_rn(make_float2(lo, hi));
    return *reinterpret_cast<unsigned*>(&b2);
}
__device__ __forceinline__ void cp_async16(unsigned smem_dst, const void* gmem_src) {
    asm volatile("cp.async.ca.shared.global [%0], [%1], 16;"
                 :: "r"(smem_dst), "l"(gmem_src) : "memory");
}

// ---------------- kernel 0: reset ----------------
__global__ void k_reset() {
    int t = threadIdx.x;
    if (t < NC) { g_sum_c[t] = 0.0; g_ss_c[t] = 0.0; }
    if (t < NR) { g_sum_r[t] = 0.0; g_ss_r[t] = 0.0; }
}

// ---------------- kernel 1: big1 = stats_child ∪ stats_root ∪ root_emb ∪ proj(mma) ----
__global__ __launch_bounds__(256)
void k_big1(const int* __restrict__ cfi, const float* __restrict__ child_num,
            const int* __restrict__ idx, const float* __restrict__ root_num,
            const int* __restrict__ root_cat, const float* __restrict__ emb_root,
            const float* __restrict__ emb_child, const float* __restrict__ W,
            float* __restrict__ out) {
    extern __shared__ float sm[];
    int bid = blockIdx.x;
    int t = threadIdx.x;
    int lane = t & 31;
    int warp = t >> 5;

    if (bid < SC_BLKS) {
        int* rid = (int*)sm;
        rid[t] = cfi[bid * 256 + t];
        __syncthreads();
        int col = t & 127;
        int r0 = (t >> 7) * 128;
        float s[8], ss[8];
#pragma unroll
        for (int u = 0; u < 8; ++u) { s[u] = 0.f; ss[u] = 0.f; }
        for (int r = r0; r < r0 + 128; r += 8) {
            float x[8];
#pragma unroll
            for (int u = 0; u < 8; ++u) {
                int g = rid[r + u];
                x[u] = __ldg(&child_num[(size_t)g * NC + col]);
            }
#pragma unroll
            for (int u = 0; u < 8; ++u) { s[u] += x[u]; ss[u] += x[u] * x[u]; }
        }
        float st  = (s[0]+s[1])+(s[2]+s[3])+((s[4]+s[5])+(s[6]+s[7]));
        float sst = (ss[0]+ss[1])+(ss[2]+ss[3])+((ss[4]+ss[5])+(ss[6]+ss[7]));
        atomicAdd(&g_sum_c[col], (double)st);
        atomicAdd(&g_ss_c[col],  (double)sst);
        return;
    }
    if (bid < RE_BASE) {
        int b = bid - SC_BLKS;
        int* rid = (int*)sm;
        if (t < 128) rid[t] = idx[b * 128 + t];
        __syncthreads();
        int col = t & 63;
        int r0 = (t >> 6) * 32;
        float s[4], ss[4];
#pragma unroll
        for (int u = 0; u < 4; ++u) { s[u] = 0.f; ss[u] = 0.f; }
        for (int r = r0; r < r0 + 32; r += 4) {
            float x[4];
#pragma unroll
            for (int u = 0; u < 4; ++u) {
                int g = rid[r + u];
                x[u] = __ldg(&root_num[(size_t)g * NR + col]);
            }
#pragma unroll
            for (int u = 0; u < 4; ++u) { s[u] += x[u]; ss[u] += x[u] * x[u]; }
        }
        atomicAdd(&g_sum_r[col], (double)((s[0]+s[1])+(s[2]+s[3])));
        atomicAdd(&g_ss_r[col],  (double)((ss[0]+ss[1])+(ss[2]+ss[3])));
        return;
    }
    if (bid < PJ_BASE) {
        // ---- root embedding copy: one warp per root row ----
        int rr = (bid - RE_BASE) * 8 + warp;
        int g = idx[rr];
        const int* cr = root_cat + (size_t)g * CR;
        float* orow = out + (size_t)rr * OUTCOLS;
#pragma unroll
        for (int c = 0; c < CR; ++c) {
            int v = cr[c];
            const float2* e = (const float2*)(emb_root + ((size_t)c * VOCAB + v) * DIM);
            *(float2*)(orow + c * DIM + lane * 2) = e[lane];
        }
        return;
    }

    // ---- proj via mma tf32: block = (c, 128 vocab rows); warp = 16 rows ----
    int pb = bid - PJ_BASE;
    int c  = pb / PTILES;
    int vbase = (pb % PTILES) * 128;

    float* Ws = sm;                               // [64][40] tf32 bits
    float* As = sm + WS_FLOATS + warp * AS_FLOATS;// [16][68] tf32 bits

    for (int i = t; i < DIM * OUTD; i += 256) {
        int o = i >> 6, d = i & 63;
        Ws[d * 40 + o] = __uint_as_float(tf32r(W[(size_t)o * KDIM + c * DIM + d]));
    }
    __syncthreads();

    int v0w = vbase + warp * 16;
    {
        int rsel = lane >> 4;
        int col  = (lane & 15) * 4;
#pragma unroll
        for (int rr = 0; rr < 8; ++rr) {
            int row = 2 * rr + rsel;
            int v = v0w + row;
            float4 e = make_float4(0.f, 0.f, 0.f, 0.f);
            if (v < VOCAB)
                e = *(const float4*)(emb_child + ((size_t)c * VOCAB + v) * DIM + col);
            float4 a;
            a.x = __uint_as_float(tf32r(e.x));
            a.y = __uint_as_float(tf32r(e.y));
            a.z = __uint_as_float(tf32r(e.z));
            a.w = __uint_as_float(tf32r(e.w));
            *(float4*)(As + row * 68 + col) = a;
        }
    }
    __syncwarp();

    float cfr[4][4];
#pragma unroll
    for (int nt = 0; nt < 4; ++nt)
#pragma unroll
        for (int j = 0; j < 4; ++j) cfr[nt][j] = 0.f;

    int gid = lane >> 2, tig = lane & 3;
#pragma unroll
    for (int kt = 0; kt < 8; ++kt) {
        int k0 = kt * 8;
        unsigned a0 = __float_as_uint(As[gid * 68 + k0 + tig]);
        unsigned a1 = __float_as_uint(As[(gid + 8) * 68 + k0 + tig]);
        unsigned a2 = __float_as_uint(As[gid * 68 + k0 + tig + 4]);
        unsigned a3 = __float_as_uint(As[(gid + 8) * 68 + k0 + tig + 4]);
#pragma unroll
        for (int nt = 0; nt < 4; ++nt) {
            unsigned b0 = __float_as_uint(Ws[(k0 + tig) * 40 + nt * 8 + gid]);
            unsigned b1 = __float_as_uint(Ws[(k0 + tig + 4) * 40 + nt * 8 + gid]);
            mma_tf32(cfr[nt][0], cfr[nt][1], cfr[nt][2], cfr[nt][3],
                     a0, a1, a2, a3, b0, b1);
        }
    }
    __syncwarp();

    // epilogue: repack fragments via smem (As dead) -> coalesced uint4 stores
    {
        unsigned* Au = (unsigned*)As;   // [16][20] pitch
#pragma unroll
        for (int nt = 0; nt < 4; ++nt) {
            int word = nt * 4 + tig;
            Au[gid * 20 + word]       = packbf(cfr[nt][0], cfr[nt][1]);
            Au[(gid + 8) * 20 + word] = packbf(cfr[nt][2], cfr[nt][3]);
        }
        __syncwarp();
        int row = lane >> 1, q = lane & 1;
        int v = v0w + row;
        if (v < VOCAB) {
            unsigned* dst = g_projp + ((size_t)c * VOCAB + v) * 16;
            *(uint4*)(dst + q * 4)       = *(uint4*)(Au + row * 20 + q * 4);
            *(uint4*)(dst + (q + 2) * 4) = *(uint4*)(Au + row * 20 + (q + 2) * 4);
        }
    }
}

// ---------------- kernel 2: finalize BN + tf32 numeric W slice ----------------
__global__ __launch_bounds__(1024)
void k_finalize(const float* __restrict__ gamma_c, const float* __restrict__ beta_c,
                const float* __restrict__ gamma_r, const float* __restrict__ beta_r,
                const float* __restrict__ W) {
    int t = threadIdx.x;
    if (t < NC) {
        double m = g_sum_c[t] * (1.0 / (double)NCHILD);
        double v = g_ss_c[t] * (1.0 / (double)NCHILD) - m * m;
        float a = gamma_c[t] * rsqrtf((float)v + EPSBN);
        g_a_c[t] = a;
        g_s_c[t] = beta_c[t] - (float)m * a;
    }
    if (t < NR) {
        double m = g_sum_r[t] * (1.0 / (double)B_ROOT);
        double v = g_ss_r[t] * (1.0 / (double)B_ROOT) - m * m;
        float a = gamma_r[t] * rsqrtf((float)v + EPSBN);
        g_a_r[t] = a;
        g_s_r[t] = beta_r[t] - (float)m * a;
    }
    for (int i = t; i < NC * OUTD; i += 1024) {
        int k = i >> 5, o = i & 31;
        g_wt[i] = __uint_as_float(tf32r(W[(size_t)o * KDIM + CC * DIM + k]));
    }
}

// ---------------- kernel 3: big2 = child (cp.async chunk0 prefetch) ∪ root-num -------
__global__ __launch_bounds__(256, 3)
void k_big2(const int* __restrict__ cfi, const int* __restrict__ child_cat,
            const float* __restrict__ child_num,
            const int* __restrict__ idx, const float* __restrict__ root_num,
            const float* __restrict__ bias,
            float* __restrict__ out) {
    extern __shared__ float sm[];
    int bid = blockIdx.x;
    int t = threadIdx.x;
    int lane = t & 31;
    int warp = t >> 5;

    if (bid >= CH_BLKS) {
        // ---- root numeric BN: 32 rows per block, 8 threads per row ----
        int r = (bid - CH_BLKS) * 32 + (t >> 3);
        int g = idx[r];
        int c8 = (t & 7) * 8;
        float4 x0 = *(const float4*)(root_num + (size_t)g * NR + c8);
        float4 x1 = *(const float4*)(root_num + (size_t)g * NR + c8 + 4);
        float4 a0 = *(const float4*)(g_a_r + c8);
        float4 a1 = *(const float4*)(g_a_r + c8 + 4);
        float4 s0 = *(const float4*)(g_s_r + c8);
        float4 s1 = *(const float4*)(g_s_r + c8 + 4);
        float4 y0, y1;
        y0.x = fmaf(x0.x, a0.x, s0.x); y0.y = fmaf(x0.y, a0.y, s0.y);
        y0.z = fmaf(x0.z, a0.z, s0.z); y0.w = fmaf(x0.w, a0.w, s0.w);
        y1.x = fmaf(x1.x, a1.x, s1.x); y1.y = fmaf(x1.y, a1.y, s1.y);
        y1.z = fmaf(x1.z, a1.z, s1.z); y1.w = fmaf(x1.w, a1.w, s1.w);
        float* orow = out + (size_t)r * OUTCOLS + CR * DIM;
        *(float4*)(orow + c8)     = y0;
        *(float4*)(orow + c8 + 4) = y1;
        return;
    }

    // ---- child: warp = one root (16 rows) ----
    float* Wn_s = sm;                                   // [128][40] tf32 bits
    float* wb   = sm + WNS_FLOATS + warp * W2_FLOATS;
    float* hs   = wb;                                   // [16][68] (alias buf[16][36])
    float* buf  = hs;
    int*   cats = (int*)(wb + 16 * 68);                 // [16][16]
    int*   gs   = cats + 256;                           // [16]

    for (int i = t; i < NC * OUTD; i += 256) {
        int k = i >> 5, o = i & 31;
        Wn_s[k * 40 + o] = g_wt[i];
    }
    __syncthreads();

    int root = bid * 8 + warp;
    if (lane < 16) gs[lane] = cfi[root * KFAN + lane];
    __syncwarp();
    {
        int e1 = lane, e2 = lane + 32;
        ((int4*)cats)[e1] = ((const int4*)(child_cat + (size_t)gs[e1 >> 2] * CC))[e1 & 3];
        ((int4*)cats)[e2] = ((const int4*)(child_cat + (size_t)gs[e2 >> 2] * CC))[e2 & 3];
    }

    // prefetch chunk-0 raw child_num into hs via cp.async (no register cost);
    // rides under the cat-gather phase below.
    int cg  = lane & 15, rof = lane >> 4;
    {
        unsigned hs_sh = (unsigned)__cvta_generic_to_shared(hs);
#pragma unroll
        for (int j = 0; j < 8; ++j) {
            int r = j * 2 + rof;
            const float* src = child_num + (size_t)gs[r] * NC + cg * 4;
            cp_async16(hs_sh + (unsigned)(r * 68 + cg * 4) * 4u, src);
        }
        asm volatile("cp.async.commit_group;" ::: "memory");
    }
    __syncwarp();

    // cooperative cat gather
    float s[16];
#pragma unroll
    for (int j = 0; j < 16; ++j) s[j] = 0.f;
    int rA = lane >> 2, m = lane & 3, rB = rA + 8;
#pragma unroll
    for (int c = 0; c < CC; ++c) {
        uint4 ua = ((const uint4*)(g_projp + ((size_t)c * VOCAB + cats[rA * 16 + c]) * 16))[m];
        uint4 ub = ((const uint4*)(g_projp + ((size_t)c * VOCAB + cats[rB * 16 + c]) * 16))[m];
        acc8(s, ua);
        acc8(s + 8, ub);
    }

    float cfr[4][4];
#pragma unroll
    for (int nt = 0; nt < 4; ++nt)
#pragma unroll
        for (int j = 0; j < 4; ++j) cfr[nt][j] = 0.f;

    int gid = lane >> 2, tig = lane & 3;

    // ---- chunk 0: wait prefetch, BN+tf32 transform in place, MMA ----
    asm volatile("cp.async.wait_group 0;" ::: "memory");
    __syncwarp();
    {
        float4 a4 = *(const float4*)(g_a_c + cg * 4);
        float4 s4 = *(const float4*)(g_s_c + cg * 4);
#pragma unroll
        for (int j = 0; j < 8; ++j) {
            int r = j * 2 + rof;
            float4 x = *(const float4*)(hs + r * 68 + cg * 4);
            uint4 hv;
            hv.x = tf32r(fmaf(x.x, a4.x, s4.x));
            hv.y = tf32r(fmaf(x.y, a4.y, s4.y));
            hv.z = tf32r(fmaf(x.z, a4.z, s4.z));
            hv.w = tf32r(fmaf(x.w, a4.w, s4.w));
            *(uint4*)(hs + r * 68 + cg * 4) = hv;
        }
    }
    __syncwarp();
#pragma unroll
    for (int kt = 0; kt < 8; ++kt) {
        int k0 = kt * 8;
        unsigned a0 = __float_as_uint(hs[gid * 68 + k0 + tig]);
        unsigned a1 = __float_as_uint(hs[(gid + 8) * 68 + k0 + tig]);
        unsigned a2 = __float_as_uint(hs[gid * 68 + k0 + tig + 4]);
        unsigned a3 = __float_as_uint(hs[(gid + 8) * 68 + k0 + tig + 4]);
        int kg = k0 + tig;
#pragma unroll
        for (int nt = 0; nt < 4; ++nt) {
            unsigned b0 = __float_as_uint(Wn_s[kg * 40 + nt * 8 + gid]);
            unsigned b1 = __float_as_uint(Wn_s[(kg + 4) * 40 + nt * 8 + gid]);
            mma_tf32(cfr[nt][0], cfr[nt][1], cfr[nt][2], cfr[nt][3],
                     a0, a1, a2, a3, b0, b1);
        }
    }
    __syncwarp();

    // ---- chunk 1: LDG stage, MMA ----
    {
        int cg2 = lane & 15, rof2 = lane >> 4;
        float4 a4 = *(const float4*)(g_a_c + 64 + cg2 * 4);
        float4 s4 = *(const float4*)(g_s_c + 64 + cg2 * 4);
#pragma unroll
        for (int j = 0; j < 8; ++j) {
            int r = j * 2 + rof2;
            float4 x = *(const float4*)(child_num + (size_t)gs[r] * NC + 64 + cg2 * 4);
            uint4 hv;
            hv.x = tf32r(fmaf(x.x, a4.x, s4.x));
            hv.y = tf32r(fmaf(x.y, a4.y, s4.y));
            hv.z = tf32r(fmaf(x.z, a4.z, s4.z));
            hv.w = tf32r(fmaf(x.w, a4.w, s4.w));
            *(uint4*)(hs + r * 68 + cg2 * 4) = hv;
        }
    }
    __syncwarp();
#pragma unroll
    for (int kt = 0; kt < 8; ++kt) {
        int k0 = kt * 8;
        unsigned a0 = __float_as_uint(hs[gid * 68 + k0 + tig]);
        unsigned a1 = __float_as_uint(hs[(gid + 8) * 68 + k0 + tig]);
        unsigned a2 = __float_as_uint(hs[gid * 68 + k0 + tig + 4]);
        unsigned a3 = __float_as_uint(hs[(gid + 8) * 68 + k0 + tig + 4]);
        int kg = 64 + k0 + tig;
#pragma unroll
        for (int nt = 0; nt < 4; ++nt) {
            unsigned b0 = __float_as_uint(Wn_s[kg * 40 + nt * 8 + gid]);
            unsigned b1 = __float_as_uint(Wn_s[(kg + 4) * 40 + nt * 8 + gid]);
            mma_tf32(cfr[nt][0], cfr[nt][1], cfr[nt][2], cfr[nt][3],
                     a0, a1, a2, a3, b0, b1);
        }
    }
    __syncwarp();

    // cat partials -> buf (aliases hs; all MMA reads done)
    *(float4*)(buf + rA * 36 + 8 * m)     = make_float4(s[0], s[1], s[2], s[3]);
    *(float4*)(buf + rA * 36 + 8 * m + 4) = make_float4(s[4], s[5], s[6], s[7]);
    *(float4*)(buf + rB * 36 + 8 * m)     = make_float4(s[8], s[9], s[10], s[11]);
    *(float4*)(buf + rB * 36 + 8 * m + 4) = make_float4(s[12], s[13], s[14], s[15]);
    __syncwarp();

    // add MMA fragments (distinct (r,o) owners)
#pragma unroll
    for (int nt = 0; nt < 4; ++nt) {
        int o0 = nt * 8 + 2 * tig;
        buf[gid * 36 + o0]           += cfr[nt][0];
        buf[gid * 36 + o0 + 1]       += cfr[nt][1];
        buf[(gid + 8) * 36 + o0]     += cfr[nt][2];
        buf[(gid + 8) * 36 + o0 + 1] += cfr[nt][3];
    }
    __syncwarp();

    // epilogue: lane = output column; relu + mean over 16 rows; coalesced store
    {
        float bp = __ldg(&bias[lane]);
        float acc = 0.f;
#pragma unroll
        for (int r = 0; r < 16; ++r)
            acc += fmaxf(buf[r * 36 + lane] + bp, 0.f);
        out[(size_t)root * OUTCOLS + CR * DIM + NR + lane] = acc * (1.0f / (float)KFAN);
    }
}

// ---------------- launch ----------------
extern "C" void kernel_launch(void* const* d_in, const int* in_sizes, int n_in,
                              void* d_out, int out_size) {
    const int *idx = nullptr, *cfi = nullptr, *root_cat = nullptr, *child_cat = nullptr;
    const float *root_num = nullptr, *child_num = nullptr;
    const float *emb_root = nullptr, *emb_child = nullptr;
    const float *W = nullptr, *bias = nullptr;
    const float *gamma_r = nullptr, *beta_r = nullptr, *gamma_c = nullptr, *beta_c = nullptr;

    for (int i = 0; i < n_in; ++i) {
        long long s = in_sizes[i];
        void* p = d_in[i];
        switch (s) {
            case 8192:      idx = (const int*)p; break;
            case 131072:    cfi = (const int*)p; break;
            case 1600000:   root_cat  = (const int*)p; break;
            case 8000000:   child_cat = (const int*)p; break;
            case 12800000:  root_num  = (const float*)p; break;
            case 64000000:  child_num = (const float*)p; break;
            case 25600000:  emb_root  = (const float*)p; break;
            case 51200000:  emb_child = (const float*)p; break;
            case 36864:     W = (const float*)p; break;
            case 32:        bias = (const float*)p; break;
            case 64:
                if (!gamma_r) gamma_r = (const float*)p; else beta_r = (const float*)p;
                break;
            case 128:
                if (!gamma_c) gamma_c = (const float*)p; else beta_c = (const float*)p;
                break;
            default: break;
        }
    }

    float* out = (float*)d_out;

    cudaFuncSetAttribute(k_big1, cudaFuncAttributeMaxDynamicSharedMemorySize, BIG1_SMEM);
    cudaFuncSetAttribute(k_big2, cudaFuncAttributeMaxDynamicSharedMemorySize, BIG2_SMEM);

    k_reset<<<1, 256>>>();
    k_big1<<<BIG1_BLKS, 256, BIG1_SMEM>>>(cfi, child_num, idx, root_num,
                                          root_cat, emb_root, emb_child, W, out);
    k_finalize<<<1, 1024>>>(gamma_c, beta_c, gamma_r, beta_r, W);
    k_big2<<<BIG2_BLKS, 256, BIG2_SMEM>>>(cfi, child_cat, child_num,
                                          idx, root_num, bias, out);
}